// round 1
// baseline (speedup 1.0000x reference)
#include <cuda_runtime.h>
#include <math.h>

#define BATCH  4
#define BC     32
#define C_     32
#define W_     14
#define HH     16
#define OUT_HW 29
#define NKL    (BC * 3 * 3)      // 288
#define CWW    (C_ * W_ * W_)    // 6272
#define POS    (W_ * W_)         // 196

// sqrt(var) cache: 4 * 6272 * 16 floats = 1.6 MB (device global, no allocation)
__device__ float g_sv[BATCH * CWW * HH];

// Prep: compute g_sv = sqrt(var), zero the output (scatter accumulates into it).
__global__ void prep_kernel(const float* __restrict__ var,
                            float* __restrict__ out, int out_n4) {
    int idx = blockIdx.x * blockDim.x + threadIdx.x;
    const int sv_n4 = BATCH * CWW * HH / 4;
    if (idx < sv_n4) {
        float4 v = reinterpret_cast<const float4*>(var)[idx];
        float4 s;
        s.x = sqrtf(v.x); s.y = sqrtf(v.y);
        s.z = sqrtf(v.z); s.w = sqrtf(v.w);
        reinterpret_cast<float4*>(g_sv)[idx] = s;
    }
    if (idx < out_n4) {
        reinterpret_cast<float4*>(out)[idx] = make_float4(0.f, 0.f, 0.f, 0.f);
    }
}

// Main: one block per (b, nkl). Each active thread owns one spatial site
// (j,i), accumulates the 4x4 (u,w) output tile over c (32) and v (4),
// then scatters via atomicAdd (RED.E.ADD.F32) into recon[b,n,2i+k,2j+l,:].
__global__ __launch_bounds__(224, 4) void conv_caps_kernel(
    const float* __restrict__ poses,   // mu: (b, CWW, 16)
    const float* __restrict__ Wt,      // (nkl, c, u, v)
    const float* __restrict__ noise,   // (b, nkl, CWW, 16)
    float* __restrict__ out)           // (b, BC, 29, 29, 16)
{
    const int nkl = blockIdx.x;
    const int b   = blockIdx.y;

    __shared__ float sW[C_ * HH];   // W[nkl] slice: [c][u][v], 2 KB
    for (int t = threadIdx.x; t < C_ * HH; t += blockDim.x)
        sW[t] = Wt[nkl * C_ * HH + t];
    __syncthreads();

    const int tid = threadIdx.x;
    if (tid >= POS) return;
    const int j = tid / W_;
    const int i = tid % W_;

    const float4* nz = reinterpret_cast<const float4*>(noise)
                       + (size_t)(b * NKL + nkl) * (CWW * HH / 4);
    const float4* mu = reinterpret_cast<const float4*>(poses)
                       + (size_t)b * (CWW * HH / 4);
    const float4* sv = reinterpret_cast<const float4*>(g_sv)
                       + (size_t)b * (CWW * HH / 4);

    float acc[16];
#pragma unroll
    for (int t = 0; t < 16; t++) acc[t] = 0.f;

#pragma unroll 2
    for (int c = 0; c < C_; c++) {
        const int base = (c * POS + tid) * 4;   // float4 index of the 64B group
        const float* wc = &sW[c * 16];          // W[c][u][v], broadcast LDS
#pragma unroll
        for (int v = 0; v < 4; v++) {
            float4 nn = nz[base + v];
            float4 mm = mu[base + v];
            float4 ss = sv[base + v];
            float4 vt;
            vt.x = fmaf(ss.x, nn.x, mm.x);
            vt.y = fmaf(ss.y, nn.y, mm.y);
            vt.z = fmaf(ss.z, nn.z, mm.z);
            vt.w = fmaf(ss.w, nn.w, mm.w);
#pragma unroll
            for (int u = 0; u < 4; u++) {
                const float wv = wc[u * 4 + v];
                acc[u * 4 + 0] = fmaf(wv, vt.x, acc[u * 4 + 0]);
                acc[u * 4 + 1] = fmaf(wv, vt.y, acc[u * 4 + 1]);
                acc[u * 4 + 2] = fmaf(wv, vt.z, acc[u * 4 + 2]);
                acc[u * 4 + 3] = fmaf(wv, vt.w, acc[u * 4 + 3]);
            }
        }
    }

    // nkl = (n*3 + k)*3 + l
    const int n = nkl / 9;
    const int k = (nkl / 3) % 3;
    const int l = nkl % 3;
    const int r  = 2 * i + k;   // output row
    const int cc = 2 * j + l;   // output col

    float* o = out + ((((size_t)b * BC + n) * OUT_HW + r) * OUT_HW + cc) * HH;
#pragma unroll
    for (int t = 0; t < 16; t++) atomicAdd(o + t, acc[t]);
}

extern "C" void kernel_launch(void* const* d_in, const int* in_sizes, int n_in,
                              void* d_out, int out_size) {
    const float* poses = (const float*)d_in[0];
    const float* var   = (const float*)d_in[1];
    const float* Wt    = (const float*)d_in[2];
    const float* noise = (const float*)d_in[3];
    float* out = (float*)d_out;

    const int out_n4 = out_size / 4;            // 430592, covers sv_n4=100352 too
    const int pt = 256;
    const int pb = (out_n4 + pt - 1) / pt;
    prep_kernel<<<pb, pt>>>(var, out, out_n4);

    dim3 grid(NKL, BATCH);
    conv_caps_kernel<<<grid, 224>>>(poses, Wt, noise, out);
}

// round 4
// speedup vs baseline: 1.4946x; 1.4946x over previous
#include <cuda_runtime.h>
#include <math.h>

#define BATCH  4
#define BC     32
#define C_     32
#define W_     14
#define HH     16
#define OUT_HW 29
#define NKL    288              // BC*3*3
#define CWW    6272             // C_*14*14
#define POS    196              // 14*14
#define G      4                // nkl group per block (mu/sv amortization)
#define NKLG   (NKL / G)        // 72

// sqrt(var) cache: 4 * 6272 * 16 floats = 1.6 MB
__device__ float g_sv[BATCH * CWW * HH];

__global__ void prep_kernel(const float* __restrict__ var,
                            float* __restrict__ out, int out_n4) {
    int idx = blockIdx.x * blockDim.x + threadIdx.x;
    const int sv_n4 = BATCH * CWW * HH / 4;
    if (idx < sv_n4) {
        float4 v = reinterpret_cast<const float4*>(var)[idx];
        float4 s;
        s.x = sqrtf(v.x); s.y = sqrtf(v.y);
        s.z = sqrtf(v.z); s.w = sqrtf(v.w);
        reinterpret_cast<float4*>(g_sv)[idx] = s;
    }
    if (idx < out_n4)
        reinterpret_cast<float4*>(out)[idx] = make_float4(0.f, 0.f, 0.f, 0.f);
}

__device__ __forceinline__ void fma4(float4& a, float s, const float4& b) {
    a.x = fmaf(s, b.x, a.x);
    a.y = fmaf(s, b.y, a.y);
    a.z = fmaf(s, b.z, a.z);
    a.w = fmaf(s, b.w, a.w);
}

// Lane mapping: lane = sl*4 + v. A 4-lane group owns one spatial site; each
// lane holds the v-th hh-row (float4 over w). Warp loads are 512B contiguous
// (perfectly coalesced). Each lane accumulates the partial sum
// acc[u][w] += W[c][u][v_lane] * vote[v_lane][w]; the v-contraction is done
// once at the end with 2 butterfly-shuffle rounds.
// Block handles G=4 consecutive nkl values so mu/sv are read once per G.
__global__ __launch_bounds__(256, 2) void conv_caps_kernel(
    const float* __restrict__ poses,   // mu: (b, CWW, 16)
    const float* __restrict__ Wt,      // (nkl, c, u, v)
    const float* __restrict__ noise,   // (b, nkl, CWW, 16)
    float* __restrict__ out)           // (b, BC, 29, 29, 16)
{
    const int nkl0   = blockIdx.x * G;
    const int b      = blockIdx.y;
    const int schunk = blockIdx.z;     // 64 sites per block

    // W transposed to [g][c][v][u] so a lane reads its 4 u-values as one LDS.128
    __shared__ __align__(16) float sWt[G][C_][4][4];
    for (int t = threadIdx.x; t < G * C_ * 16; t += blockDim.x) {
        int g  = t >> 9;          // / 512
        int r  = t & 511;
        int c  = r >> 4;
        int u  = (r >> 2) & 3;
        int vv = r & 3;
        sWt[g][c][vv][u] = Wt[(nkl0 + g) * (C_ * 16) + r];
    }
    __syncthreads();

    const int lane = threadIdx.x & 31;
    const int warp = threadIdx.x >> 5;
    const int v    = lane & 3;
    const int sl   = lane >> 2;
    const int site = schunk * 64 + warp * 8 + sl;
    const bool active = (site < POS);

    float4 acc[G][4];
#pragma unroll
    for (int g = 0; g < G; g++)
#pragma unroll
        for (int u = 0; u < 4; u++)
            acc[g][u] = make_float4(0.f, 0.f, 0.f, 0.f);

    if (active) {
        const size_t bq = (size_t)b * (CWW * HH / 4);
        const float4* mu4 = reinterpret_cast<const float4*>(poses) + bq;
        const float4* sv4 = reinterpret_cast<const float4*>(g_sv) + bq;
        const float4* nz4[G];
#pragma unroll
        for (int g = 0; g < G; g++)
            nz4[g] = reinterpret_cast<const float4*>(noise)
                   + (size_t)(b * NKL + nkl0 + g) * (CWW * HH / 4);

        const int sbase = site * 4 + v;
#pragma unroll 2
        for (int c = 0; c < C_; c++) {
            const int fidx = c * (POS * 4) + sbase;
            float4 mm = mu4[fidx];
            float4 ss = sv4[fidx];
            float4 nn[G];
#pragma unroll
            for (int g = 0; g < G; g++) nn[g] = nz4[g][fidx];
#pragma unroll
            for (int g = 0; g < G; g++) {
                float4 vt;
                vt.x = fmaf(ss.x, nn[g].x, mm.x);
                vt.y = fmaf(ss.y, nn[g].y, mm.y);
                vt.z = fmaf(ss.z, nn[g].z, mm.z);
                vt.w = fmaf(ss.w, nn[g].w, mm.w);
                const float4 w4 =
                    *reinterpret_cast<const float4*>(&sWt[g][c][v][0]);
                fma4(acc[g][0], w4.x, vt);
                fma4(acc[g][1], w4.y, vt);
                fma4(acc[g][2], w4.z, vt);
                fma4(acc[g][3], w4.w, vt);
            }
        }
    }

    // Reduce the v-partials across each 4-lane group (butterfly, full mask;
    // all lanes reach here, inactive lanes contribute zeros).
#pragma unroll
    for (int g = 0; g < G; g++)
#pragma unroll
        for (int u = 0; u < 4; u++) {
            float4 a = acc[g][u];
            a.x += __shfl_xor_sync(0xffffffffu, a.x, 1);
            a.y += __shfl_xor_sync(0xffffffffu, a.y, 1);
            a.z += __shfl_xor_sync(0xffffffffu, a.z, 1);
            a.w += __shfl_xor_sync(0xffffffffu, a.w, 1);
            a.x += __shfl_xor_sync(0xffffffffu, a.x, 2);
            a.y += __shfl_xor_sync(0xffffffffu, a.y, 2);
            a.z += __shfl_xor_sync(0xffffffffu, a.z, 2);
            a.w += __shfl_xor_sync(0xffffffffu, a.w, 2);
            acc[g][u] = a;
        }

    if (active) {
        const int j = site / W_;
        const int i = site % W_;
#pragma unroll
        for (int g = 0; g < G; g++) {
            const int nkl = nkl0 + g;
            const int n = nkl / 9;
            const int k = (nkl / 3) % 3;
            const int l = nkl % 3;
            const int r  = 2 * i + k;
            const int cc = 2 * j + l;
            // lane v scatters the u==v float4 (group covers all 16 values)
            float4 a = (v == 0) ? acc[g][0]
                     : (v == 1) ? acc[g][1]
                     : (v == 2) ? acc[g][2]
                                : acc[g][3];
            float* o = out + ((((size_t)b * BC + n) * OUT_HW + r) * OUT_HW + cc) * HH
                           + v * 4;
            atomicAdd(o + 0, a.x);
            atomicAdd(o + 1, a.y);
            atomicAdd(o + 2, a.z);
            atomicAdd(o + 3, a.w);
        }
    }
}

extern "C" void kernel_launch(void* const* d_in, const int* in_sizes, int n_in,
                              void* d_out, int out_size) {
    const float* poses = (const float*)d_in[0];
    const float* var   = (const float*)d_in[1];
    const float* Wt    = (const float*)d_in[2];
    const float* noise = (const float*)d_in[3];
    float* out = (float*)d_out;

    const int out_n4 = out_size / 4;
    const int pt = 256;
    const int pb = (out_n4 + pt - 1) / pt;
    prep_kernel<<<pb, pt>>>(var, out, out_n4);

    dim3 grid(NKLG, BATCH, 4);   // 72 nkl-groups x 4 batch x 4 site-chunks
    conv_caps_kernel<<<grid, 256>>>(poses, Wt, noise, out);
}